// round 2
// baseline (speedup 1.0000x reference)
#include <cuda_runtime.h>

typedef unsigned long long ull;

#define TOKENS 100352   // 256 windows * 392 tokens
#define NVOL   392

// Scratch (static device allocations are allowed)
__device__ float g_qkv[(size_t)TOKENS * 384];   // [token][384] : q(0:128)*scale, k(128:256), v(256:384)
__device__ float g_att[(size_t)TOKENS * 128];   // attention output, token-major

__device__ __forceinline__ void fma2(ull &acc, ull a, ull b) {
    asm("fma.rn.f32x2 %0, %1, %2, %0;" : "+l"(acc) : "l"(a), "l"(b));
}
__device__ __forceinline__ float hsum2(ull p) {
    return __uint_as_float((unsigned)p) + __uint_as_float((unsigned)(p >> 32));
}
__device__ __forceinline__ ull lds2(const float* p) {
    return *(const ull*)p;
}

// token index -> source/dest element offset in [B,T,H,W,C] with cyclic shift (+4,+3,+3 mod dims)
__device__ __forceinline__ int token_img_offset(int m) {
    int win = m / 392;
    int l   = m - win * 392;
    int b   = win >> 7;
    int w2  = win & 127;
    int it  = w2 >> 6, ih = (w2 >> 3) & 7, iw = w2 & 7;
    int lt  = l / 49; int r = l - lt * 49;
    int lh  = r / 7;  int lw = r - lh * 7;
    int t = (it * 8 + lt + 4) & 15;
    int h = ih * 7 + lh + 3; if (h >= 56) h -= 56;
    int w = iw * 7 + lw + 3; if (w >= 56) w -= 56;
    return (((b * 16 + t) * 56 + h) * 56 + w) * 128;
}

// ---------------------------------------------------------------------------
// Kernel 1: QKV GEMM with fused shift+window gather.
// grid (1568, 6), block 256 (16x16), BM=BN=64, K=128 resident in smem.
// ---------------------------------------------------------------------------
__global__ __launch_bounds__(256) void qkv_kernel(
    const float* __restrict__ x, const float* __restrict__ w,
    const float* __restrict__ bias)
{
    extern __shared__ float sm[];
    float* As = sm;                         // [64][130]
    float* Bs = sm + 64 * 130;              // [64][130]
    int* rowsrc = (int*)(sm + 2 * 64 * 130);

    int m0 = blockIdx.x * 64;
    int n0 = blockIdx.y * 64;
    int tid = threadIdx.x;

    if (tid < 64) rowsrc[tid] = token_img_offset(m0 + tid);
    __syncthreads();

    #pragma unroll
    for (int i = tid; i < 64 * 32; i += 256) {
        int rr = i >> 5, c4 = i & 31;
        float4 v = *(const float4*)(x + rowsrc[rr] + c4 * 4);
        float* d = As + rr * 130 + c4 * 4;
        d[0] = v.x; d[1] = v.y; d[2] = v.z; d[3] = v.w;
    }
    #pragma unroll
    for (int i = tid; i < 64 * 32; i += 256) {
        int rr = i >> 5, c4 = i & 31;
        float4 v = *(const float4*)(w + (n0 + rr) * 128 + c4 * 4);
        float* d = Bs + rr * 130 + c4 * 4;
        d[0] = v.x; d[1] = v.y; d[2] = v.z; d[3] = v.w;
    }
    __syncthreads();

    int tx = tid & 15, ty = tid >> 4;
    ull acc[16];
    #pragma unroll
    for (int i = 0; i < 16; i++) acc[i] = 0ull;

    const float* ap = As + ty * 130;
    const float* bp = Bs + tx * 130;
    #pragma unroll 8
    for (int kp = 0; kp < 64; kp++) {
        ull a2[4], b2[4];
        #pragma unroll
        for (int i = 0; i < 4; i++) a2[i] = lds2(ap + i * (16 * 130) + 2 * kp);
        #pragma unroll
        for (int j = 0; j < 4; j++) b2[j] = lds2(bp + j * (16 * 130) + 2 * kp);
        #pragma unroll
        for (int i = 0; i < 4; i++)
            #pragma unroll
            for (int j = 0; j < 4; j++)
                fma2(acc[i * 4 + j], a2[i], b2[j]);
    }

    #pragma unroll
    for (int j = 0; j < 4; j++) {
        int n = n0 + tx + 16 * j;
        float bv = bias[n];
        float sc = (n < 128) ? 0.17677669529663687f : 1.0f;  // q * hd^-0.5
        #pragma unroll
        for (int i = 0; i < 4; i++) {
            int m = m0 + ty + 16 * i;
            g_qkv[(size_t)m * 384 + n] = (hsum2(acc[i * 4 + j]) + bv) * sc;
        }
    }
}

// ---------------------------------------------------------------------------
// Kernel 2: fused attention. One block per (window, head). 224 threads (16x14).
// Smem: Ks[392][34] | Vt[32][394] | Qs[56][34] | Ss[56][394] | rid[392]
// ---------------------------------------------------------------------------
__global__ __launch_bounds__(224) void attn_kernel(const float* __restrict__ rpb)
{
    extern __shared__ float sm[];
    float* Ks = sm;                          // 392*34  = 13328
    float* Vt = Ks + 392 * 34;               // 32*394  = 12608
    float* Qs = Vt + 32 * 394;               // 56*34   = 1904
    float* Ss = Qs + 56 * 34;                // 56*394  = 22064
    unsigned char* rid = (unsigned char*)(Ss + 56 * 394);

    int bx = blockIdx.x;
    int win = bx >> 2, head = bx & 3;
    int tid = threadIdx.x;

    const float* qbase = g_qkv + (size_t)win * (392 * 384) + head * 32;
    const float* kbase = qbase + 128;
    const float* vbase = qbase + 256;

    // region ids for shift mask (nonzero only at boundary blocks)
    int w2 = win & 127;
    int bt = ((w2 >> 6) == 1), bh = (((w2 >> 3) & 7) == 7), bw = ((w2 & 7) == 7);
    for (int l = tid; l < 392; l += 224) {
        int lt = l / 49; int r = l - lt * 49; int lh = r / 7; int lw = r - lh * 7;
        int rt = bt ? ((lt < 4) ? 1 : 2) : 0;
        int rh = bh ? ((lh < 4) ? 1 : 2) : 0;
        int rw = bw ? ((lw < 4) ? 1 : 2) : 0;
        rid[l] = (unsigned char)(rt * 9 + rh * 3 + rw);
    }
    // load K [j][d] and V transposed [d][j]
    for (int i = tid; i < 392 * 8; i += 224) {
        int j = i >> 3, c4 = i & 7;
        float4 v = *(const float4*)(kbase + (size_t)j * 384 + c4 * 4);
        float* d = Ks + j * 34 + c4 * 4;
        d[0] = v.x; d[1] = v.y; d[2] = v.z; d[3] = v.w;
    }
    for (int i = tid; i < 392 * 8; i += 224) {
        int j = i >> 3, c4 = i & 7;
        float4 v = *(const float4*)(vbase + (size_t)j * 384 + c4 * 4);
        int d0 = c4 * 4;
        Vt[(d0 + 0) * 394 + j] = v.x;
        Vt[(d0 + 1) * 394 + j] = v.y;
        Vt[(d0 + 2) * 394 + j] = v.z;
        Vt[(d0 + 3) * 394 + j] = v.w;
    }

    int tx = tid & 15, ty = tid >> 4;        // ty in 0..13
    int warp = tid >> 5, lane = tid & 31;
    const float* bhp = rpb + (size_t)head * (392 * 392);

    for (int qt = 0; qt < 7; qt++) {
        int q0 = qt * 56;
        for (int i = tid; i < 56 * 8; i += 224) {
            int qq = i >> 3, c4 = i & 7;
            float4 v = *(const float4*)(qbase + (size_t)(q0 + qq) * 384 + c4 * 4);
            float* d = Qs + qq * 34 + c4 * 4;
            d[0] = v.x; d[1] = v.y; d[2] = v.z; d[3] = v.w;
        }
        __syncthreads();   // Qs ready; also guards Ss reuse vs prior PV

        // ---- S = Q K^T (+bias +mask), 7 j-subtiles of 64 ----
        const float* qp = Qs + ty * 34;
        for (int jt = 0; jt < 7; jt++) {
            const float* kp_ = Ks + (jt * 64 + tx) * 34;
            ull acc[16];
            #pragma unroll
            for (int i = 0; i < 16; i++) acc[i] = 0ull;
            #pragma unroll
            for (int kp = 0; kp < 16; kp++) {
                ull a2[4], b2[4];
                #pragma unroll
                for (int i = 0; i < 4; i++) a2[i] = lds2(qp + i * (14 * 34) + 2 * kp);
                #pragma unroll
                for (int j = 0; j < 4; j++) b2[j] = lds2(kp_ + j * (16 * 34) + 2 * kp);
                #pragma unroll
                for (int i = 0; i < 4; i++)
                    #pragma unroll
                    for (int j = 0; j < 4; j++)
                        fma2(acc[i * 4 + j], a2[i], b2[j]);
            }
            #pragma unroll
            for (int j = 0; j < 4; j++) {
                int jg = jt * 64 + tx + 16 * j;
                if (jg < 392) {
                    unsigned char rj = rid[jg];
                    #pragma unroll
                    for (int i = 0; i < 4; i++) {
                        int q = ty + 14 * i;
                        int qg = q0 + q;
                        float mv = (rid[qg] == rj) ? 0.f : -100.f;
                        float v = hsum2(acc[i * 4 + j])
                                + __ldg(bhp + (size_t)qg * 392 + jg) + mv;
                        Ss[q * 394 + jg] = v;
                    }
                }
            }
        }
        __syncthreads();

        // ---- softmax over rows (7 warps x 8 rows) ----
        for (int r = warp; r < 56; r += 7) {
            float* row = Ss + r * 394;
            float mx = -1e30f;
            for (int j = lane; j < 392; j += 32) mx = fmaxf(mx, row[j]);
            #pragma unroll
            for (int o = 16; o > 0; o >>= 1) mx = fmaxf(mx, __shfl_xor_sync(0xffffffffu, mx, o));
            float s = 0.f;
            for (int j = lane; j < 392; j += 32) { float e = __expf(row[j] - mx); row[j] = e; s += e; }
            #pragma unroll
            for (int o = 16; o > 0; o >>= 1) s += __shfl_xor_sync(0xffffffffu, s, o);
            float inv = 1.0f / s;
            for (int j = lane; j < 392; j += 32) row[j] *= inv;
        }
        __syncthreads();

        // ---- out = P V : [56][32], pairs over j ----
        ull acc2[8];
        #pragma unroll
        for (int i = 0; i < 8; i++) acc2[i] = 0ull;
        const float* sp  = Ss + ty * 394;
        const float* vp0 = Vt + tx * 394;
        const float* vp1 = Vt + (tx + 16) * 394;
        #pragma unroll 2
        for (int jp = 0; jp < 196; jp++) {
            ull b0 = lds2(vp0 + 2 * jp);
            ull b1 = lds2(vp1 + 2 * jp);
            #pragma unroll
            for (int i = 0; i < 4; i++) {
                ull a = lds2(sp + i * (14 * 394) + 2 * jp);
                fma2(acc2[i * 2 + 0], a, b0);
                fma2(acc2[i * 2 + 1], a, b1);
            }
        }
        #pragma unroll
        for (int i = 0; i < 4; i++) {
            int qg = q0 + ty + 14 * i;
            size_t ob = ((size_t)win * 392 + qg) * 128 + head * 32;
            g_att[ob + tx]      = hsum2(acc2[i * 2 + 0]);
            g_att[ob + tx + 16] = hsum2(acc2[i * 2 + 1]);
        }
    }
}

// ---------------------------------------------------------------------------
// Kernel 3: proj GEMM with fused un-partition + inverse-roll scatter.
// grid (1568, 2), block 256.
// ---------------------------------------------------------------------------
__global__ __launch_bounds__(256) void proj_kernel(
    const float* __restrict__ w, const float* __restrict__ bias,
    float* __restrict__ out)
{
    extern __shared__ float sm[];
    float* As = sm;
    float* Bs = sm + 64 * 130;
    int* rowdst = (int*)(sm + 2 * 64 * 130);

    int m0 = blockIdx.x * 64;
    int n0 = blockIdx.y * 64;
    int tid = threadIdx.x;

    if (tid < 64) rowdst[tid] = token_img_offset(m0 + tid);
    __syncthreads();

    #pragma unroll
    for (int i = tid; i < 64 * 32; i += 256) {
        int rr = i >> 5, c4 = i & 31;
        float4 v = *(const float4*)(g_att + (size_t)(m0 + rr) * 128 + c4 * 4);
        float* d = As + rr * 130 + c4 * 4;
        d[0] = v.x; d[1] = v.y; d[2] = v.z; d[3] = v.w;
    }
    #pragma unroll
    for (int i = tid; i < 64 * 32; i += 256) {
        int rr = i >> 5, c4 = i & 31;
        float4 v = *(const float4*)(w + (n0 + rr) * 128 + c4 * 4);
        float* d = Bs + rr * 130 + c4 * 4;
        d[0] = v.x; d[1] = v.y; d[2] = v.z; d[3] = v.w;
    }
    __syncthreads();

    int tx = tid & 15, ty = tid >> 4;
    ull acc[16];
    #pragma unroll
    for (int i = 0; i < 16; i++) acc[i] = 0ull;

    const float* ap = As + ty * 130;
    const float* bp = Bs + tx * 130;
    #pragma unroll 8
    for (int kp = 0; kp < 64; kp++) {
        ull a2[4], b2[4];
        #pragma unroll
        for (int i = 0; i < 4; i++) a2[i] = lds2(ap + i * (16 * 130) + 2 * kp);
        #pragma unroll
        for (int j = 0; j < 4; j++) b2[j] = lds2(bp + j * (16 * 130) + 2 * kp);
        #pragma unroll
        for (int i = 0; i < 4; i++)
            #pragma unroll
            for (int j = 0; j < 4; j++)
                fma2(acc[i * 4 + j], a2[i], b2[j]);
    }

    #pragma unroll
    for (int j = 0; j < 4; j++) {
        int n = n0 + tx + 16 * j;
        float bv = bias[n];
        #pragma unroll
        for (int i = 0; i < 4; i++) {
            out[rowdst[ty + 16 * i] + n] = hsum2(acc[i * 4 + j]) + bv;
        }
    }
}

// ---------------------------------------------------------------------------
extern "C" void kernel_launch(void* const* d_in, const int* in_sizes, int n_in,
                              void* d_out, int out_size)
{
    const float* x   = (const float*)d_in[0];
    const float* qw  = (const float*)d_in[1];
    const float* qb  = (const float*)d_in[2];
    const float* pw  = (const float*)d_in[3];
    const float* pb  = (const float*)d_in[4];
    const float* rpb = (const float*)d_in[5];
    float* out = (float*)d_out;

    const int smemG = (2 * 64 * 130) * 4 + 64 * 4;            // 66,816 B
    const int smemA = (392*34 + 32*394 + 56*34 + 56*394) * 4 + 448;  // ~200 KB

    cudaFuncSetAttribute(qkv_kernel,  cudaFuncAttributeMaxDynamicSharedMemorySize, smemG);
    cudaFuncSetAttribute(attn_kernel, cudaFuncAttributeMaxDynamicSharedMemorySize, smemA);
    cudaFuncSetAttribute(proj_kernel, cudaFuncAttributeMaxDynamicSharedMemorySize, smemG);

    qkv_kernel<<<dim3(1568, 6), 256, smemG>>>(x, qw, qb);
    attn_kernel<<<1024, 224, smemA>>>(rpb);
    proj_kernel<<<dim3(1568, 2), 256, smemG>>>(pw, pb, out);
}

// round 3
// speedup vs baseline: 1.2810x; 1.2810x over previous
#include <cuda_runtime.h>

typedef unsigned long long ull;

#define TOKENS 100352   // 256 windows * 392 tokens

__device__ float g_qkv[(size_t)TOKENS * 384];   // [token][384]: q*scale | k | v
__device__ float g_att[(size_t)TOKENS * 128];   // attention output, token-major

__device__ __forceinline__ void fma2(ull &acc, ull a, ull b) {
    asm("fma.rn.f32x2 %0, %1, %2, %0;" : "+l"(acc) : "l"(a), "l"(b));
}
__device__ __forceinline__ float hsum2(ull p) {
    return __uint_as_float((unsigned)p) + __uint_as_float((unsigned)(p >> 32));
}
__device__ __forceinline__ ull lds2(const float* p) { return *(const ull*)p; }

// token -> element offset in [B,T,H,W,C] with cyclic shift (+4,+3,+3)
__device__ __forceinline__ int token_img_offset(int m) {
    int win = m / 392;
    int l   = m - win * 392;
    int b   = win >> 7;
    int w2  = win & 127;
    int it  = w2 >> 6, ih = (w2 >> 3) & 7, iw = w2 & 7;
    int lt  = l / 49; int r = l - lt * 49;
    int lh  = r / 7;  int lw = r - lh * 7;
    int t = (it * 8 + lt + 4) & 15;
    int h = ih * 7 + lh + 3; if (h >= 56) h -= 56;
    int w = iw * 7 + lw + 3; if (w >= 56) w -= 56;
    return (((b * 16 + t) * 56 + h) * 56 + w) * 128;
}

// ---------------------------------------------------------------------------
// Kernel 1: QKV GEMM, fused gather. 128x128 tile, 256 thr, 8x8 micro, f32x2-K.
// ---------------------------------------------------------------------------
__global__ __launch_bounds__(256, 1) void qkv_kernel(
    const float* __restrict__ x, const float* __restrict__ w,
    const float* __restrict__ bias)
{
    extern __shared__ float sm[];
    float* As = sm;                          // [128][130]
    float* Bs = sm + 128 * 130;              // [128][130]
    int* rowsrc = (int*)(sm + 2 * 128 * 130);

    int m0 = blockIdx.x * 128;
    int n0 = blockIdx.y * 128;
    int tid = threadIdx.x;

    if (tid < 128) rowsrc[tid] = token_img_offset(m0 + tid);
    __syncthreads();

    for (int i = tid; i < 128 * 32; i += 256) {
        int rr = i >> 5, c4 = i & 31;
        float4 v = *(const float4*)(x + rowsrc[rr] + c4 * 4);
        float* d = As + rr * 130 + c4 * 4;
        d[0] = v.x; d[1] = v.y; d[2] = v.z; d[3] = v.w;
    }
    for (int i = tid; i < 128 * 32; i += 256) {
        int rr = i >> 5, c4 = i & 31;
        float4 v = *(const float4*)(w + (size_t)(n0 + rr) * 128 + c4 * 4);
        float* d = Bs + rr * 130 + c4 * 4;
        d[0] = v.x; d[1] = v.y; d[2] = v.z; d[3] = v.w;
    }
    __syncthreads();

    int tx = tid & 15, ty = tid >> 4;
    ull acc[8][8];
    #pragma unroll
    for (int i = 0; i < 8; i++)
        #pragma unroll
        for (int j = 0; j < 8; j++) acc[i][j] = 0ull;

    const float* ap = As + ty * 130;
    const float* bp = Bs + tx * 130;
    #pragma unroll 4
    for (int kp = 0; kp < 64; kp++) {
        ull a[8], b[8];
        #pragma unroll
        for (int i = 0; i < 8; i++) a[i] = lds2(ap + i * (16 * 130) + 2 * kp);
        #pragma unroll
        for (int j = 0; j < 8; j++) b[j] = lds2(bp + j * (16 * 130) + 2 * kp);
        #pragma unroll
        for (int i = 0; i < 8; i++)
            #pragma unroll
            for (int j = 0; j < 8; j++)
                fma2(acc[i][j], a[i], b[j]);
    }

    #pragma unroll
    for (int j = 0; j < 8; j++) {
        int n = n0 + tx + 16 * j;
        float bv = bias[n];
        float sc = (n < 128) ? 0.17677669529663687f : 1.0f;
        #pragma unroll
        for (int i = 0; i < 8; i++) {
            int m = m0 + ty + 16 * i;
            g_qkv[(size_t)m * 384 + n] = (hsum2(acc[i][j]) + bv) * sc;
        }
    }
}

// ---------------------------------------------------------------------------
// Kernel 2: fused attention. Block = (win, head), 224 threads (7 warps).
// ---------------------------------------------------------------------------
template<int NJ>
__device__ __forceinline__ void s_pass(
    const float* __restrict__ Qs, const float* __restrict__ Ks,
    float* __restrict__ Ss, const float* __restrict__ bias_q0,
    const unsigned char* __restrict__ rid, int q0, int jbase, int ty, int tx)
{
    ull acc[8][NJ];
    #pragma unroll
    for (int i = 0; i < 8; i++)
        #pragma unroll
        for (int jj = 0; jj < NJ; jj++) acc[i][jj] = 0ull;

    const float* qp = Qs + ty * 8 * 34;
    const float* kp = Ks + (jbase + tx) * 34;
    #pragma unroll 4
    for (int k2 = 0; k2 < 16; k2++) {
        ull a[8], b[NJ];
        #pragma unroll
        for (int i = 0; i < 8; i++) a[i] = lds2(qp + i * 34 + 2 * k2);
        #pragma unroll
        for (int jj = 0; jj < NJ; jj++) b[jj] = lds2(kp + jj * (32 * 34) + 2 * k2);
        #pragma unroll
        for (int i = 0; i < 8; i++)
            #pragma unroll
            for (int jj = 0; jj < NJ; jj++)
                fma2(acc[i][jj], a[i], b[jj]);
    }

    #pragma unroll
    for (int jj = 0; jj < NJ; jj++) {
        int j = jbase + tx + 32 * jj;
        if (j < 392) {
            unsigned char rj = rid[j];
            #pragma unroll
            for (int i = 0; i < 8; i++) {
                int q = ty * 8 + i;
                float mv = (rid[q0 + q] == rj) ? 0.f : -100.f;
                float v = hsum2(acc[i][jj])
                        + __ldg(bias_q0 + (size_t)q * 392 + j) + mv;
                Ss[q * 394 + j] = v;
            }
        }
    }
}

__global__ __launch_bounds__(224, 1) void attn_kernel(const float* __restrict__ rpb)
{
    extern __shared__ float sm[];
    float* Ks = sm;                          // [392][34]
    float* Vt = Ks + 392 * 34;               // [32][394]
    float* Qs = Vt + 32 * 394;               // [56][34]
    float* Ss = Qs + 56 * 34;                // [56][394]; reused as part[7][56*33]
    float* sinv = Ss + 56 * 394;             // [56]
    unsigned char* rid = (unsigned char*)(sinv + 56);

    int bx = blockIdx.x;
    int win = bx >> 2, head = bx & 3;
    int tid = threadIdx.x;

    const float* qbase = g_qkv + (size_t)win * (392 * 384) + head * 32;
    const float* kbase = qbase + 128;
    const float* vbase = qbase + 256;

    int w2 = win & 127;
    int bt = ((w2 >> 6) == 1), bh = (((w2 >> 3) & 7) == 7), bw = ((w2 & 7) == 7);
    for (int l = tid; l < 392; l += 224) {
        int lt = l / 49; int r = l - lt * 49; int lh = r / 7; int lw = r - lh * 7;
        int rt = bt ? ((lt < 4) ? 1 : 2) : 0;
        int rh = bh ? ((lh < 4) ? 1 : 2) : 0;
        int rw = bw ? ((lw < 4) ? 1 : 2) : 0;
        rid[l] = (unsigned char)(rt * 9 + rh * 3 + rw);
    }
    for (int i = tid; i < 392 * 8; i += 224) {
        int j = i >> 3, c4 = i & 7;
        float4 v = *(const float4*)(kbase + (size_t)j * 384 + c4 * 4);
        float* d = Ks + j * 34 + c4 * 4;
        d[0] = v.x; d[1] = v.y; d[2] = v.z; d[3] = v.w;
    }
    for (int i = tid; i < 392 * 8; i += 224) {
        int j = i >> 3, c4 = i & 7;
        float4 v = *(const float4*)(vbase + (size_t)j * 384 + c4 * 4);
        int d0 = c4 * 4;
        Vt[(d0 + 0) * 394 + j] = v.x;
        Vt[(d0 + 1) * 394 + j] = v.y;
        Vt[(d0 + 2) * 394 + j] = v.z;
        Vt[(d0 + 3) * 394 + j] = v.w;
    }

    int ty = tid >> 5, tx = tid & 31;        // ty = warp id (0..6)
    int lane = tid & 31;
    int qg = lane >> 2, dg = lane & 3;       // PV lane map
    const float* bhp = rpb + (size_t)head * (392 * 392);

    for (int qt = 0; qt < 7; qt++) {
        int q0 = qt * 56;
        for (int i = tid; i < 56 * 8; i += 224) {
            int qq = i >> 3, c4 = i & 7;
            float4 v = *(const float4*)(qbase + (size_t)(q0 + qq) * 384 + c4 * 4);
            float* d = Qs + qq * 34 + c4 * 4;
            d[0] = v.x; d[1] = v.y; d[2] = v.z; d[3] = v.w;
        }
        __syncthreads();   // Qs ready (also orders Ks/Vt/rid on qt==0)

        const float* bias_q0 = bhp + (size_t)q0 * 392;
        s_pass<8>(Qs, Ks, Ss, bias_q0, rid, q0, 0,   ty, tx);
        s_pass<5>(Qs, Ks, Ss, bias_q0, rid, q0, 256, ty, tx);
        __syncthreads();

        // softmax stats: rows hold unnormalized exp, sinv[q] = 1/sum
        for (int r = ty; r < 56; r += 7) {
            float* row = Ss + r * 394;
            float mx = -1e30f;
            for (int j = lane; j < 392; j += 32) mx = fmaxf(mx, row[j]);
            #pragma unroll
            for (int o = 16; o > 0; o >>= 1) mx = fmaxf(mx, __shfl_xor_sync(0xffffffffu, mx, o));
            float s = 0.f;
            for (int j = lane; j < 392; j += 32) { float e = __expf(row[j] - mx); row[j] = e; s += e; }
            #pragma unroll
            for (int o = 16; o > 0; o >>= 1) s += __shfl_xor_sync(0xffffffffu, s, o);
            if (lane == 0) sinv[r] = 1.0f / s;
        }
        __syncthreads();

        // PV: warp ty owns j-pairs [ty*28, ty*28+28); thread tile 7q x 8d
        ull acc[7][8];
        #pragma unroll
        for (int i = 0; i < 7; i++)
            #pragma unroll
            for (int k = 0; k < 8; k++) acc[i][k] = 0ull;

        const float* sp = Ss + qg * 394;
        const float* vp = Vt + (dg * 8) * 394;
        int jp0 = ty * 28;
        #pragma unroll 2
        for (int p = 0; p < 28; p++) {
            int jp2 = (jp0 + p) * 2;
            ull a[7], b[8];
            #pragma unroll
            for (int i = 0; i < 7; i++) a[i] = lds2(sp + i * (8 * 394) + jp2);
            #pragma unroll
            for (int k = 0; k < 8; k++) b[k] = lds2(vp + k * 394 + jp2);
            #pragma unroll
            for (int i = 0; i < 7; i++)
                #pragma unroll
                for (int k = 0; k < 8; k++)
                    fma2(acc[i][k], a[i], b[k]);
        }
        __syncthreads();   // all warps done reading Ss

        // store per-warp partials into Ss region: part[w][q][d], q-stride 33
        float* part = Ss;
        #pragma unroll
        for (int i = 0; i < 7; i++) {
            int q = qg + 8 * i;
            #pragma unroll
            for (int k = 0; k < 8; k++)
                part[ty * 1848 + q * 33 + dg * 8 + k] = hsum2(acc[i][k]);
        }
        __syncthreads();

        // reduce 7 partials, apply 1/sum, write out
        #pragma unroll
        for (int r = 0; r < 8; r++) {
            int o = tid + 224 * r;          // 8*224 = 1792 = 56*32
            int q = o >> 5, d = o & 31;
            float s = 0.f;
            #pragma unroll
            for (int w = 0; w < 7; w++) s += part[w * 1848 + q * 33 + d];
            s *= sinv[q];
            g_att[((size_t)win * 392 + q0 + q) * 128 + head * 32 + d] = s;
        }
        __syncthreads();   // before next qt overwrites Ss/Qs
    }
}

// ---------------------------------------------------------------------------
// Kernel 3: proj GEMM, fused scatter. 128x128 tile, 8x8 micro.
// ---------------------------------------------------------------------------
__global__ __launch_bounds__(256, 1) void proj_kernel(
    const float* __restrict__ w, const float* __restrict__ bias,
    float* __restrict__ out)
{
    extern __shared__ float sm[];
    float* As = sm;
    float* Bs = sm + 128 * 130;
    int* rowdst = (int*)(sm + 2 * 128 * 130);

    int m0 = blockIdx.x * 128;
    int n0 = blockIdx.y * 128;
    int tid = threadIdx.x;

    if (tid < 128) rowdst[tid] = token_img_offset(m0 + tid);
    __syncthreads();

    for (int i = tid; i < 128 * 32; i += 256) {
        int rr = i >> 5, c4 = i & 31;
        float4 v = *(const float4*)(g_att + (size_t)(m0 + rr) * 128 + c4 * 4);
        float* d = As + rr * 130 + c4 * 4;
        d[0] = v.x; d[1] = v.y; d[2] = v.z; d[3] = v.w;
    }
    for (int i = tid; i < 128 * 32; i += 256) {
        int rr = i >> 5, c4 = i & 31;
        float4 v = *(const float4*)(w + (size_t)(n0 + rr) * 128 + c4 * 4);
        float* d = Bs + rr * 130 + c4 * 4;
        d[0] = v.x; d[1] = v.y; d[2] = v.z; d[3] = v.w;
    }
    __syncthreads();

    int tx = tid & 15, ty = tid >> 4;
    ull acc[8][8];
    #pragma unroll
    for (int i = 0; i < 8; i++)
        #pragma unroll
        for (int j = 0; j < 8; j++) acc[i][j] = 0ull;

    const float* ap = As + ty * 130;
    const float* bp = Bs + tx * 130;
    #pragma unroll 4
    for (int kp = 0; kp < 64; kp++) {
        ull a[8], b[8];
        #pragma unroll
        for (int i = 0; i < 8; i++) a[i] = lds2(ap + i * (16 * 130) + 2 * kp);
        #pragma unroll
        for (int j = 0; j < 8; j++) b[j] = lds2(bp + j * (16 * 130) + 2 * kp);
        #pragma unroll
        for (int i = 0; i < 8; i++)
            #pragma unroll
            for (int j = 0; j < 8; j++)
                fma2(acc[i][j], a[i], b[j]);
    }

    #pragma unroll
    for (int j = 0; j < 8; j++) {
        int n = n0 + tx + 16 * j;
        float bv = bias[n];
        #pragma unroll
        for (int i = 0; i < 8; i++) {
            out[rowdst[ty + 16 * i] + n] = hsum2(acc[i][j]) + bv;
        }
    }
}

// ---------------------------------------------------------------------------
extern "C" void kernel_launch(void* const* d_in, const int* in_sizes, int n_in,
                              void* d_out, int out_size)
{
    const float* x   = (const float*)d_in[0];
    const float* qw  = (const float*)d_in[1];
    const float* qb  = (const float*)d_in[2];
    const float* pw  = (const float*)d_in[3];
    const float* pb  = (const float*)d_in[4];
    const float* rpb = (const float*)d_in[5];
    float* out = (float*)d_out;

    const int smemG = (2 * 128 * 130) * 4 + 128 * 4;  // 133,632 B
    const int smemA = (392*34 + 32*394 + 56*34 + 56*394 + 56) * 4 + 392 + 8; // ~200 KB

    cudaFuncSetAttribute(qkv_kernel,  cudaFuncAttributeMaxDynamicSharedMemorySize, smemG);
    cudaFuncSetAttribute(attn_kernel, cudaFuncAttributeMaxDynamicSharedMemorySize, smemA);
    cudaFuncSetAttribute(proj_kernel, cudaFuncAttributeMaxDynamicSharedMemorySize, smemG);

    qkv_kernel<<<dim3(784, 3), 256, smemG>>>(x, qw, qb);
    attn_kernel<<<1024, 224, smemA>>>(rpb);
    proj_kernel<<<dim3(784, 1), 256, smemG>>>(pw, pb, out);
}

// round 4
// speedup vs baseline: 1.4770x; 1.1530x over previous
#include <cuda_runtime.h>

typedef unsigned long long ull;

#define TOKENS 100352   // 256 windows * 392 tokens

__device__ float g_qkv[(size_t)TOKENS * 384];   // [token][384]: q*scale | k | v
__device__ float g_att[(size_t)TOKENS * 128];   // attention output, token-major

__device__ __forceinline__ void fma2(ull &acc, ull a, ull b) {
    asm("fma.rn.f32x2 %0, %1, %2, %0;" : "+l"(acc) : "l"(a), "l"(b));
}
__device__ __forceinline__ float hsum2(ull p) {
    return __uint_as_float((unsigned)p) + __uint_as_float((unsigned)(p >> 32));
}
__device__ __forceinline__ ull lds2(const float* p) { return *(const ull*)p; }

// token -> element offset in [B,T,H,W,C] with cyclic shift (+4,+3,+3)
__device__ __forceinline__ int token_img_offset(int m) {
    int win = m / 392;
    int l   = m - win * 392;
    int b   = win >> 7;
    int w2  = win & 127;
    int it  = w2 >> 6, ih = (w2 >> 3) & 7, iw = w2 & 7;
    int lt  = l / 49; int r = l - lt * 49;
    int lh  = r / 7;  int lw = r - lh * 7;
    int t = (it * 8 + lt + 4) & 15;
    int h = ih * 7 + lh + 3; if (h >= 56) h -= 56;
    int w = iw * 7 + lw + 3; if (w >= 56) w -= 56;
    return (((b * 16 + t) * 56 + h) * 56 + w) * 128;
}

// ---------------------------------------------------------------------------
// Kernel 1: QKV GEMM, fused gather. 128x128 tile, 512 thr, 8m x 4n micro.
// ---------------------------------------------------------------------------
__global__ __launch_bounds__(512, 1) void qkv_kernel(
    const float* __restrict__ x, const float* __restrict__ w,
    const float* __restrict__ bias)
{
    extern __shared__ float sm[];
    float* As = sm;                          // [128][130]
    float* Bs = sm + 128 * 130;              // [128][130]
    int* rowsrc = (int*)(sm + 2 * 128 * 130);

    int m0 = blockIdx.x * 128;
    int n0 = blockIdx.y * 128;
    int tid = threadIdx.x;

    if (tid < 128) rowsrc[tid] = token_img_offset(m0 + tid);
    __syncthreads();

    for (int i = tid; i < 128 * 32; i += 512) {
        int rr = i >> 5, c4 = i & 31;
        float4 v = *(const float4*)(x + rowsrc[rr] + c4 * 4);
        float* d = As + rr * 130 + c4 * 4;
        d[0] = v.x; d[1] = v.y; d[2] = v.z; d[3] = v.w;
    }
    for (int i = tid; i < 128 * 32; i += 512) {
        int rr = i >> 5, c4 = i & 31;
        float4 v = *(const float4*)(w + (size_t)(n0 + rr) * 128 + c4 * 4);
        float* d = Bs + rr * 130 + c4 * 4;
        d[0] = v.x; d[1] = v.y; d[2] = v.z; d[3] = v.w;
    }
    __syncthreads();

    int tn = tid & 31;        // lane -> n
    int tm = tid >> 5;        // warp -> m group
    ull acc[8][4];
    #pragma unroll
    for (int i = 0; i < 8; i++)
        #pragma unroll
        for (int j = 0; j < 4; j++) acc[i][j] = 0ull;

    const float* ap = As + tm * 130;
    const float* bp = Bs + tn * 130;
    #pragma unroll 4
    for (int kp = 0; kp < 64; kp++) {
        ull a[8], b[4];
        #pragma unroll
        for (int i = 0; i < 8; i++) a[i] = lds2(ap + i * (16 * 130) + 2 * kp);
        #pragma unroll
        for (int j = 0; j < 4; j++) b[j] = lds2(bp + j * (32 * 130) + 2 * kp);
        #pragma unroll
        for (int i = 0; i < 8; i++)
            #pragma unroll
            for (int j = 0; j < 4; j++)
                fma2(acc[i][j], a[i], b[j]);
    }

    #pragma unroll
    for (int j = 0; j < 4; j++) {
        int n = n0 + tn + 32 * j;
        float bv = bias[n];
        float sc = (n < 128) ? 0.17677669529663687f : 1.0f;
        #pragma unroll
        for (int i = 0; i < 8; i++) {
            int m = m0 + tm + 16 * i;
            g_qkv[(size_t)m * 384 + n] = (hsum2(acc[i][j]) + bv) * sc;
        }
    }
}

// ---------------------------------------------------------------------------
// Kernel 2: fused attention. Block = (win, head), 448 threads (14 warps).
// ---------------------------------------------------------------------------
template<int NC>
__device__ __forceinline__ void s_pass(
    const float* __restrict__ Qs, const float* __restrict__ Ks,
    float* __restrict__ Ss, const float* __restrict__ bias_q0,
    const unsigned char* __restrict__ rid, int q0, int qb, int c0, int tx)
{
    ull acc[8][NC];
    #pragma unroll
    for (int i = 0; i < 8; i++)
        #pragma unroll
        for (int u = 0; u < NC; u++) acc[i][u] = 0ull;

    const float* qp = Qs + qb * 34;
    #pragma unroll 4
    for (int k2 = 0; k2 < 16; k2++) {
        ull a[8], b[NC];
        #pragma unroll
        for (int i = 0; i < 8; i++) a[i] = lds2(qp + i * 34 + 2 * k2);
        #pragma unroll
        for (int u = 0; u < NC; u++)
            b[u] = lds2(Ks + (tx + 32 * (c0 + 2 * u)) * 34 + 2 * k2);
        #pragma unroll
        for (int i = 0; i < 8; i++)
            #pragma unroll
            for (int u = 0; u < NC; u++)
                fma2(acc[i][u], a[i], b[u]);
    }

    #pragma unroll
    for (int u = 0; u < NC; u++) {
        int j = tx + 32 * (c0 + 2 * u);
        if (j < 392) {
            unsigned char rj = rid[j];
            #pragma unroll
            for (int i = 0; i < 8; i++) {
                int q = qb + i;
                float mv = (rid[q0 + q] == rj) ? 0.f : -100.f;
                float v = hsum2(acc[i][u])
                        + __ldg(bias_q0 + (size_t)q * 392 + j) + mv;
                Ss[q * 394 + j] = v;
            }
        }
    }
}

__global__ __launch_bounds__(448, 1) void attn_kernel(const float* __restrict__ rpb)
{
    extern __shared__ float sm[];
    float* Ks = sm;                          // [392][34]
    float* Vt = Ks + 392 * 34;               // [32][394]
    float* Qs = Vt + 32 * 394;               // [56][34]
    float* Ss = Qs + 56 * 34;                // [56][394]; part[7][56][32] aliased
    float* sinv = Ss + 56 * 394;             // [56]
    unsigned char* rid = (unsigned char*)(sinv + 56);

    int bx = blockIdx.x;
    int win = bx >> 2, head = bx & 3;
    int tid = threadIdx.x;

    const float* qbase = g_qkv + (size_t)win * (392 * 384) + head * 32;
    const float* kbase = qbase + 128;
    const float* vbase = qbase + 256;

    int w2 = win & 127;
    int bt = ((w2 >> 6) == 1), bh = (((w2 >> 3) & 7) == 7), bw = ((w2 & 7) == 7);
    for (int l = tid; l < 392; l += 448) {
        int lt = l / 49; int r = l - lt * 49; int lh = r / 7; int lw = r - lh * 7;
        int rt = bt ? ((lt < 4) ? 1 : 2) : 0;
        int rh = bh ? ((lh < 4) ? 1 : 2) : 0;
        int rw = bw ? ((lw < 4) ? 1 : 2) : 0;
        rid[l] = (unsigned char)(rt * 9 + rh * 3 + rw);
    }
    for (int i = tid; i < 392 * 8; i += 448) {
        int j = i >> 3, c4 = i & 7;
        float4 v = *(const float4*)(kbase + (size_t)j * 384 + c4 * 4);
        float* d = Ks + j * 34 + c4 * 4;
        d[0] = v.x; d[1] = v.y; d[2] = v.z; d[3] = v.w;
    }
    for (int i = tid; i < 392 * 8; i += 448) {
        int j = i >> 3, c4 = i & 7;
        float4 v = *(const float4*)(vbase + (size_t)j * 384 + c4 * 4);
        int d0 = c4 * 4;
        Vt[(d0 + 0) * 394 + j] = v.x;
        Vt[(d0 + 1) * 394 + j] = v.y;
        Vt[(d0 + 2) * 394 + j] = v.z;
        Vt[(d0 + 3) * 394 + j] = v.w;
    }

    int ty = tid >> 5, tx = tid & 31;        // ty = warp id (0..13)
    int qg7 = ty >> 1, jh = ty & 1;          // S-phase: q-group, j-half
    int qb = qg7 * 8;
    int js = ty >> 1, dh = ty & 1;           // PV: j-slice, d-half
    int qg = tx >> 2, dg = tx & 3;           // PV lane map
    const float* bhp = rpb + (size_t)head * (392 * 392);

    for (int qt = 0; qt < 7; qt++) {
        int q0 = qt * 56;
        {   // Q tile load: exactly 448 elements of float4
            int qq = tid >> 3, c4 = tid & 7;
            float4 v = *(const float4*)(qbase + (size_t)(q0 + qq) * 384 + c4 * 4);
            float* d = Qs + qq * 34 + c4 * 4;
            d[0] = v.x; d[1] = v.y; d[2] = v.z; d[3] = v.w;
        }
        __syncthreads();

        const float* bias_q0 = bhp + (size_t)q0 * 392;
        if (jh == 0) {
            s_pass<4>(Qs, Ks, Ss, bias_q0, rid, q0, qb, 0, tx);
            s_pass<3>(Qs, Ks, Ss, bias_q0, rid, q0, qb, 8, tx);
        } else {
            s_pass<4>(Qs, Ks, Ss, bias_q0, rid, q0, qb, 1, tx);
            s_pass<2>(Qs, Ks, Ss, bias_q0, rid, q0, qb, 9, tx);
        }
        __syncthreads();

        // softmax stats: 4 rows per warp; rows end as unnormalized exp
        #pragma unroll
        for (int rr = 0; rr < 4; rr++) {
            int r = ty * 4 + rr;
            float* row = Ss + r * 394;
            float mx = -1e30f;
            for (int j = tx; j < 392; j += 32) mx = fmaxf(mx, row[j]);
            #pragma unroll
            for (int o = 16; o > 0; o >>= 1) mx = fmaxf(mx, __shfl_xor_sync(0xffffffffu, mx, o));
            float s = 0.f;
            for (int j = tx; j < 392; j += 32) { float e = __expf(row[j] - mx); row[j] = e; s += e; }
            #pragma unroll
            for (int o = 16; o > 0; o >>= 1) s += __shfl_xor_sync(0xffffffffu, s, o);
            if (tx == 0) sinv[r] = 1.0f / s;
        }
        __syncthreads();

        // PV: warp (js, dh): j-pairs [js*28, js*28+28), d in [dh*16, dh*16+16)
        // thread: q = qg + 8i (i<7), d = dh*16 + dg*4 + (0..3)
        ull acc[7][4];
        #pragma unroll
        for (int i = 0; i < 7; i++)
            #pragma unroll
            for (int k = 0; k < 4; k++) acc[i][k] = 0ull;

        const float* sp = Ss + qg * 394;
        const float* vp = Vt + (dh * 16 + dg * 4) * 394;
        int jp0 = js * 28;
        #pragma unroll 2
        for (int p = 0; p < 28; p++) {
            int j2 = (jp0 + p) * 2;
            ull a[7], b[4];
            #pragma unroll
            for (int i = 0; i < 7; i++) a[i] = lds2(sp + i * (8 * 394) + j2);
            #pragma unroll
            for (int k = 0; k < 4; k++) b[k] = lds2(vp + k * 394 + j2);
            #pragma unroll
            for (int i = 0; i < 7; i++)
                #pragma unroll
                for (int k = 0; k < 4; k++)
                    fma2(acc[i][k], a[i], b[k]);
        }
        __syncthreads();   // all warps done reading Ss

        // partials: part[js][q][d], d-halves disjoint
        float* part = Ss;
        #pragma unroll
        for (int i = 0; i < 7; i++) {
            float4 v;
            v.x = hsum2(acc[i][0]); v.y = hsum2(acc[i][1]);
            v.z = hsum2(acc[i][2]); v.w = hsum2(acc[i][3]);
            *(float4*)(part + js * 1792 + (qg + 8 * i) * 32 + dh * 16 + dg * 4) = v;
        }
        __syncthreads();

        // reduce 7 partials, apply 1/sum, write out (448*4 = 1792 = 56*32)
        #pragma unroll
        for (int r = 0; r < 4; r++) {
            int o = tid + 448 * r;
            int q = o >> 5, d = o & 31;
            float s = 0.f;
            #pragma unroll
            for (int ww = 0; ww < 7; ww++) s += part[ww * 1792 + q * 32 + d];
            s *= sinv[q];
            g_att[((size_t)win * 392 + q0 + q) * 128 + head * 32 + d] = s;
        }
        __syncthreads();   // before next qt overwrites Qs/Ss
    }
}

// ---------------------------------------------------------------------------
// Kernel 3: proj GEMM, fused scatter. 128x128 tile, 512 thr, 8x4 micro.
// ---------------------------------------------------------------------------
__global__ __launch_bounds__(512, 1) void proj_kernel(
    const float* __restrict__ w, const float* __restrict__ bias,
    float* __restrict__ out)
{
    extern __shared__ float sm[];
    float* As = sm;
    float* Bs = sm + 128 * 130;
    int* rowdst = (int*)(sm + 2 * 128 * 130);

    int m0 = blockIdx.x * 128;
    int tid = threadIdx.x;

    if (tid < 128) rowdst[tid] = token_img_offset(m0 + tid);
    __syncthreads();

    for (int i = tid; i < 128 * 32; i += 512) {
        int rr = i >> 5, c4 = i & 31;
        float4 v = *(const float4*)(g_att + (size_t)(m0 + rr) * 128 + c4 * 4);
        float* d = As + rr * 130 + c4 * 4;
        d[0] = v.x; d[1] = v.y; d[2] = v.z; d[3] = v.w;
    }
    for (int i = tid; i < 128 * 32; i += 512) {
        int rr = i >> 5, c4 = i & 31;
        float4 v = *(const float4*)(w + (size_t)rr * 128 + c4 * 4);
        float* d = Bs + rr * 130 + c4 * 4;
        d[0] = v.x; d[1] = v.y; d[2] = v.z; d[3] = v.w;
    }
    __syncthreads();

    int tn = tid & 31;
    int tm = tid >> 5;
    ull acc[8][4];
    #pragma unroll
    for (int i = 0; i < 8; i++)
        #pragma unroll
        for (int j = 0; j < 4; j++) acc[i][j] = 0ull;

    const float* ap = As + tm * 130;
    const float* bp = Bs + tn * 130;
    #pragma unroll 4
    for (int kp = 0; kp < 64; kp++) {
        ull a[8], b[4];
        #pragma unroll
        for (int i = 0; i < 8; i++) a[i] = lds2(ap + i * (16 * 130) + 2 * kp);
        #pragma unroll
        for (int j = 0; j < 4; j++) b[j] = lds2(bp + j * (32 * 130) + 2 * kp);
        #pragma unroll
        for (int i = 0; i < 8; i++)
            #pragma unroll
            for (int j = 0; j < 4; j++)
                fma2(acc[i][j], a[i], b[j]);
    }

    #pragma unroll
    for (int j = 0; j < 4; j++) {
        int n = tn + 32 * j;
        float bv = bias[n];
        #pragma unroll
        for (int i = 0; i < 8; i++) {
            out[rowdst[tm + 16 * i] + n] = hsum2(acc[i][j]) + bv;
        }
    }
}

// ---------------------------------------------------------------------------
extern "C" void kernel_launch(void* const* d_in, const int* in_sizes, int n_in,
                              void* d_out, int out_size)
{
    const float* x   = (const float*)d_in[0];
    const float* qw  = (const float*)d_in[1];
    const float* qb  = (const float*)d_in[2];
    const float* pw  = (const float*)d_in[3];
    const float* pb  = (const float*)d_in[4];
    const float* rpb = (const float*)d_in[5];
    float* out = (float*)d_out;

    const int smemG = (2 * 128 * 130) * 4 + 128 * 4;  // 133,632 B
    const int smemA = (392*34 + 32*394 + 56*34 + 56*394 + 56) * 4 + 392 + 8; // ~200 KB

    cudaFuncSetAttribute(qkv_kernel,  cudaFuncAttributeMaxDynamicSharedMemorySize, smemG);
    cudaFuncSetAttribute(attn_kernel, cudaFuncAttributeMaxDynamicSharedMemorySize, smemA);
    cudaFuncSetAttribute(proj_kernel, cudaFuncAttributeMaxDynamicSharedMemorySize, smemG);

    qkv_kernel<<<dim3(784, 3), 512, smemG>>>(x, qw, qb);
    attn_kernel<<<1024, 448, smemA>>>(rpb);
    proj_kernel<<<784, 512, smemG>>>(pw, pb, out);
}

// round 5
// speedup vs baseline: 2.1167x; 1.4331x over previous
#include <cuda_runtime.h>

#define TOKENS 100352   // 256 windows * 392 tokens

__device__ float g_qkv[(size_t)TOKENS * 384];   // [token][384]: q*scale | k | v
__device__ float g_att[(size_t)TOKENS * 128];   // attention out, token-major

__device__ __forceinline__ unsigned rna(float f) {
    unsigned u; asm("cvt.rna.tf32.f32 %0, %1;" : "=r"(u) : "f"(f)); return u;
}
__device__ __forceinline__ void mma8(float* d, const unsigned* a, const unsigned* b) {
    asm volatile("mma.sync.aligned.m16n8k8.row.col.f32.tf32.tf32.f32 "
        "{%0,%1,%2,%3}, {%4,%5,%6,%7}, {%8,%9}, {%0,%1,%2,%3};"
        : "+f"(d[0]), "+f"(d[1]), "+f"(d[2]), "+f"(d[3])
        : "r"(a[0]), "r"(a[1]), "r"(a[2]), "r"(a[3]), "r"(b[0]), "r"(b[1]));
}
__device__ __forceinline__ unsigned f2u(float f) { return __float_as_uint(f); }

// token -> element offset in [B,T,H,W,C] with cyclic shift (+4,+3,+3)
__device__ __forceinline__ int token_img_offset(int m) {
    int win = m / 392;
    int l   = m - win * 392;
    int b   = win >> 7;
    int w2  = win & 127;
    int it  = w2 >> 6, ih = (w2 >> 3) & 7, iw = w2 & 7;
    int lt  = l / 49; int r = l - lt * 49;
    int lh  = r / 7;  int lw = r - lh * 7;
    int t = (it * 8 + lt + 4) & 15;
    int h = ih * 7 + lh + 3; if (h >= 56) h -= 56;
    int w = iw * 7 + lw + 3; if (w >= 56) w -= 56;
    return (((b * 16 + t) * 56 + h) * 56 + w) * 128;
}

// ---------------------------------------------------------------------------
// Kernel 1: QKV GEMM (3xTF32), fused gather. 128x128 tile, 512 thr.
// Warp grid 4(m)x4(n): warp does 32 rows x 32 cols = 2x4 mma tiles.
// ---------------------------------------------------------------------------
__global__ __launch_bounds__(512, 2) void qkv_kernel(
    const float* __restrict__ x, const float* __restrict__ w,
    const float* __restrict__ bias)
{
    extern __shared__ float sm[];
    float* Ah = sm;                 // [128][36]
    float* Al = Ah + 4608;
    float* Bh = Al + 4608;
    float* Bl = Bh + 4608;
    int* rowsrc = (int*)(Bl + 4608);

    int m0 = blockIdx.x * 128, n0 = blockIdx.y * 128;
    int tid = threadIdx.x;
    if (tid < 128) rowsrc[tid] = token_img_offset(m0 + tid);
    __syncthreads();

    int lane = tid & 31, warp = tid >> 5;
    int wm = warp >> 2, wn = warp & 3;

    float d[2][4][4];
    #pragma unroll
    for (int mi = 0; mi < 2; mi++)
        #pragma unroll
        for (int nj = 0; nj < 4; nj++)
            #pragma unroll
            for (int r = 0; r < 4; r++) d[mi][nj][r] = 0.f;

    for (int kc = 0; kc < 4; kc++) {
        #pragma unroll
        for (int it = 0; it < 2; it++) {
            int idx = tid + it * 512;            // 0..1023
            int r = idx >> 3, f4 = idx & 7;      // row, which float4 (8 per 32-col chunk)
            float4 va = *(const float4*)(x + rowsrc[r] + kc * 32 + f4 * 4);
            float* ah = Ah + r * 36 + f4 * 4;
            float* al = Al + r * 36 + f4 * 4;
            float hx;
            hx = __uint_as_float(rna(va.x)); ah[0] = hx; al[0] = __uint_as_float(rna(va.x - hx));
            hx = __uint_as_float(rna(va.y)); ah[1] = hx; al[1] = __uint_as_float(rna(va.y - hx));
            hx = __uint_as_float(rna(va.z)); ah[2] = hx; al[2] = __uint_as_float(rna(va.z - hx));
            hx = __uint_as_float(rna(va.w)); ah[3] = hx; al[3] = __uint_as_float(rna(va.w - hx));
            float4 vb = *(const float4*)(w + (size_t)(n0 + r) * 128 + kc * 32 + f4 * 4);
            float* bh = Bh + r * 36 + f4 * 4;
            float* bl = Bl + r * 36 + f4 * 4;
            hx = __uint_as_float(rna(vb.x)); bh[0] = hx; bl[0] = __uint_as_float(rna(vb.x - hx));
            hx = __uint_as_float(rna(vb.y)); bh[1] = hx; bl[1] = __uint_as_float(rna(vb.y - hx));
            hx = __uint_as_float(rna(vb.z)); bh[2] = hx; bl[2] = __uint_as_float(rna(vb.z - hx));
            hx = __uint_as_float(rna(vb.w)); bh[3] = hx; bl[3] = __uint_as_float(rna(vb.w - hx));
        }
        __syncthreads();

        #pragma unroll
        for (int ks = 0; ks < 4; ks++) {
            int ar = wm * 32 + (lane >> 2), ac = ks * 8 + (lane & 3);
            unsigned ahf[2][4], alf[2][4];
            #pragma unroll
            for (int mi = 0; mi < 2; mi++) {
                int base = (ar + mi * 16) * 36 + ac;
                ahf[mi][0] = f2u(Ah[base]);         ahf[mi][1] = f2u(Ah[base + 8 * 36]);
                ahf[mi][2] = f2u(Ah[base + 4]);     ahf[mi][3] = f2u(Ah[base + 8 * 36 + 4]);
                alf[mi][0] = f2u(Al[base]);         alf[mi][1] = f2u(Al[base + 8 * 36]);
                alf[mi][2] = f2u(Al[base + 4]);     alf[mi][3] = f2u(Al[base + 8 * 36 + 4]);
            }
            int bn = wn * 32 + (lane >> 2), bk = ks * 8 + (lane & 3);
            unsigned bhf[4][2], blf[4][2];
            #pragma unroll
            for (int nj = 0; nj < 4; nj++) {
                int bb = (bn + nj * 8) * 36 + bk;
                bhf[nj][0] = f2u(Bh[bb]); bhf[nj][1] = f2u(Bh[bb + 4]);
                blf[nj][0] = f2u(Bl[bb]); blf[nj][1] = f2u(Bl[bb + 4]);
            }
            #pragma unroll
            for (int mi = 0; mi < 2; mi++)
                #pragma unroll
                for (int nj = 0; nj < 4; nj++) {
                    mma8(d[mi][nj], ahf[mi], bhf[nj]);
                    mma8(d[mi][nj], ahf[mi], blf[nj]);
                    mma8(d[mi][nj], alf[mi], bhf[nj]);
                }
        }
        __syncthreads();
    }

    #pragma unroll
    for (int mi = 0; mi < 2; mi++) {
        int row = m0 + wm * 32 + mi * 16 + (lane >> 2);
        #pragma unroll
        for (int nj = 0; nj < 4; nj++) {
            int col = n0 + wn * 32 + nj * 8 + (lane & 3) * 2;
            float sc = (col < 128) ? 0.17677669529663687f : 1.0f;
            float2 bv = *(const float2*)(bias + col);
            float2 o0, o1;
            o0.x = (d[mi][nj][0] + bv.x) * sc; o0.y = (d[mi][nj][1] + bv.y) * sc;
            o1.x = (d[mi][nj][2] + bv.x) * sc; o1.y = (d[mi][nj][3] + bv.y) * sc;
            *(float2*)(g_qkv + (size_t)row * 384 + col) = o0;
            *(float2*)(g_qkv + (size_t)(row + 8) * 384 + col) = o1;
        }
    }
}

// ---------------------------------------------------------------------------
// Kernel 2: fused attention (1xTF32 mma). Block = (win, head), 512 thr.
// Smem: Ks[392][36] | Vs[392][40] | Qs[64][36] | Ss[64][396] | sinv[64] | rid
// ---------------------------------------------------------------------------
__global__ __launch_bounds__(512, 1) void attn_kernel(const float* __restrict__ rpb)
{
    extern __shared__ float sm[];
    float* Ks = sm;                     // 392*36 = 14112
    float* Vs = Ks + 14112;             // 392*40 = 15680
    float* Qs = Vs + 15680;             // 64*36  = 2304
    float* Ss = Qs + 2304;              // 64*396 = 25344
    float* sinv = Ss + 25344;           // 64
    unsigned char* rid = (unsigned char*)(sinv + 64);

    int bx = blockIdx.x;
    int win = bx >> 2, head = bx & 3;
    int tid = threadIdx.x;

    const float* qbase = g_qkv + (size_t)win * (392 * 384) + head * 32;
    const float* kbase = qbase + 128;
    const float* vbase = qbase + 256;

    // region ids for shift mask
    int w2 = win & 127;
    int bt = ((w2 >> 6) == 1), bh = (((w2 >> 3) & 7) == 7), bw = ((w2 & 7) == 7);
    for (int l = tid; l < 392; l += 512) {
        int lt = l / 49; int r = l - lt * 49; int lh = r / 7; int lw = r - lh * 7;
        int rt = bt ? ((lt < 4) ? 1 : 2) : 0;
        int rh = bh ? ((lh < 4) ? 1 : 2) : 0;
        int rw = bw ? ((lw < 4) ? 1 : 2) : 0;
        rid[l] = (unsigned char)(rt * 9 + rh * 3 + rw);
    }
    if (tid < 288) Qs[56 * 36 + tid] = 0.f;   // zero Q pad rows (56..63)

    // K, V loads (RN-rounded to tf32)
    for (int i = tid; i < 392 * 32; i += 512) {
        int j = i >> 5, c = i & 31;
        Ks[j * 36 + c] = __uint_as_float(rna(kbase[(size_t)j * 384 + c]));
    }
    for (int i = tid; i < 392 * 32; i += 512) {
        int j = i >> 5, c = i & 31;
        Vs[j * 40 + c] = __uint_as_float(rna(vbase[(size_t)j * 384 + c]));
    }

    int lane = tid & 31, warp = tid >> 5;
    int wm = warp >> 2, wn = warp & 3;
    const float* bhp = rpb + (size_t)head * (392 * 392);

    for (int qt = 0; qt < 7; qt++) {
        int q0 = qt * 56;
        for (int i = tid; i < 56 * 32; i += 512) {
            int q = i >> 5, c = i & 31;
            Qs[q * 36 + c] = __uint_as_float(rna(qbase[(size_t)(q0 + q) * 384 + c]));
        }
        __syncthreads();

        // ---- S = Q K^T : warp (wm, wn) does m-tile wm, n-tiles wn+4t ----
        float acc[13][4];
        #pragma unroll
        for (int t = 0; t < 13; t++)
            #pragma unroll
            for (int r = 0; r < 4; r++) acc[t][r] = 0.f;

        #pragma unroll
        for (int ks = 0; ks < 4; ks++) {
            int ar = wm * 16 + (lane >> 2), ac = ks * 8 + (lane & 3);
            unsigned a[4];
            a[0] = f2u(Qs[ar * 36 + ac]);       a[1] = f2u(Qs[(ar + 8) * 36 + ac]);
            a[2] = f2u(Qs[ar * 36 + ac + 4]);   a[3] = f2u(Qs[(ar + 8) * 36 + ac + 4]);
            #pragma unroll
            for (int t = 0; t < 12; t++) {
                int j = (wn + 4 * t) * 8 + (lane >> 2);
                unsigned b[2] = { f2u(Ks[j * 36 + ac]), f2u(Ks[j * 36 + ac + 4]) };
                mma8(acc[t], a, b);
            }
            if (wn == 0) {
                int j = 48 * 8 + (lane >> 2);
                unsigned b[2] = { f2u(Ks[j * 36 + ac]), f2u(Ks[j * 36 + ac + 4]) };
                mma8(acc[12], a, b);
            }
        }
        // epilogue: +bias +mask -> Ss
        {
            int qr = wm * 16 + (lane >> 2);          // < 56 always
            unsigned char rq0 = rid[q0 + qr];
            unsigned char rq1 = (wm < 3) ? rid[q0 + qr + 8] : (unsigned char)0;
            const float* br0 = bhp + (size_t)(q0 + qr) * 392;
            const float* br1 = bhp + (size_t)(q0 + qr + 8) * 392;
            #pragma unroll
            for (int t = 0; t < 13; t++) {
                if (t == 12 && wn != 0) break;
                int j = ((t < 12) ? (wn + 4 * t) : 48) * 8 + (lane & 3) * 2;
                unsigned char rj0 = rid[j], rj1 = rid[j + 1];
                float2 b0 = *(const float2*)(br0 + j);
                Ss[qr * 396 + j]     = acc[t][0] + b0.x + ((rq0 == rj0) ? 0.f : -100.f);
                Ss[qr * 396 + j + 1] = acc[t][1] + b0.y + ((rq0 == rj1) ? 0.f : -100.f);
                if (wm < 3) {
                    float2 b1 = *(const float2*)(br1 + j);
                    Ss[(qr + 8) * 396 + j]     = acc[t][2] + b1.x + ((rq1 == rj0) ? 0.f : -100.f);
                    Ss[(qr + 8) * 396 + j + 1] = acc[t][3] + b1.y + ((rq1 == rj1) ? 0.f : -100.f);
                }
            }
        }
        __syncthreads();

        // ---- softmax rows: store RN-rounded exp, sinv = 1/sum ----
        for (int r = warp; r < 56; r += 16) {
            float* row = Ss + r * 396;
            float mx = -1e30f;
            for (int j = lane; j < 392; j += 32) mx = fmaxf(mx, row[j]);
            #pragma unroll
            for (int o = 16; o > 0; o >>= 1) mx = fmaxf(mx, __shfl_xor_sync(0xffffffffu, mx, o));
            float s = 0.f;
            for (int j = lane; j < 392; j += 32) {
                float e = __uint_as_float(rna(__expf(row[j] - mx)));
                row[j] = e; s += e;
            }
            #pragma unroll
            for (int o = 16; o > 0; o >>= 1) s += __shfl_xor_sync(0xffffffffu, s, o);
            if (lane == 0) sinv[r] = 1.0f / s;
        }
        __syncthreads();

        // ---- PV: warp (wm, wn) -> 16x8 output tile, k over 392 ----
        {
            float pacc[4] = {0.f, 0.f, 0.f, 0.f};
            int par = wm * 16 + (lane >> 2);
            int pbd = wn * 8 + (lane >> 2);
            #pragma unroll 4
            for (int ks = 0; ks < 49; ks++) {
                int k0 = ks * 8;
                unsigned a[4], b[2];
                int ac = k0 + (lane & 3);
                a[0] = f2u(Ss[par * 396 + ac]);       a[1] = f2u(Ss[(par + 8) * 396 + ac]);
                a[2] = f2u(Ss[par * 396 + ac + 4]);   a[3] = f2u(Ss[(par + 8) * 396 + ac + 4]);
                int jb = k0 + (lane & 3);
                b[0] = f2u(Vs[jb * 40 + pbd]);
                b[1] = f2u(Vs[(jb + 4) * 40 + pbd]);
                mma8(pacc, a, b);
            }
            int dc = wn * 8 + (lane & 3) * 2;
            float si0 = sinv[par];
            size_t ob0 = ((size_t)win * 392 + q0 + par) * 128 + head * 32 + dc;
            float2 o0; o0.x = pacc[0] * si0; o0.y = pacc[1] * si0;
            *(float2*)(g_att + ob0) = o0;
            if (wm < 3) {
                float si1 = sinv[par + 8];
                size_t ob1 = ob0 + 8 * 128;
                float2 o1; o1.x = pacc[2] * si1; o1.y = pacc[3] * si1;
                *(float2*)(g_att + ob1) = o1;
            }
        }
        __syncthreads();   // before next qt overwrites Qs/Ss
    }
}

// ---------------------------------------------------------------------------
// Kernel 3: proj GEMM (3xTF32), fused scatter. 128x128 tile, 512 thr.
// ---------------------------------------------------------------------------
__global__ __launch_bounds__(512, 2) void proj_kernel(
    const float* __restrict__ w, const float* __restrict__ bias,
    float* __restrict__ out)
{
    extern __shared__ float sm[];
    float* Ah = sm;
    float* Al = Ah + 4608;
    float* Bh = Al + 4608;
    float* Bl = Bh + 4608;
    int* rowdst = (int*)(Bl + 4608);

    int m0 = blockIdx.x * 128;
    int tid = threadIdx.x;
    if (tid < 128) rowdst[tid] = token_img_offset(m0 + tid);
    __syncthreads();

    int lane = tid & 31, warp = tid >> 5;
    int wm = warp >> 2, wn = warp & 3;

    float d[2][4][4];
    #pragma unroll
    for (int mi = 0; mi < 2; mi++)
        #pragma unroll
        for (int nj = 0; nj < 4; nj++)
            #pragma unroll
            for (int r = 0; r < 4; r++) d[mi][nj][r] = 0.f;

    for (int kc = 0; kc < 4; kc++) {
        #pragma unroll
        for (int it = 0; it < 2; it++) {
            int idx = tid + it * 512;
            int r = idx >> 3, f4 = idx & 7;
            float4 va = *(const float4*)(g_att + (size_t)(m0 + r) * 128 + kc * 32 + f4 * 4);
            float* ah = Ah + r * 36 + f4 * 4;
            float* al = Al + r * 36 + f4 * 4;
            float hx;
            hx = __uint_as_float(rna(va.x)); ah[0] = hx; al[0] = __uint_as_float(rna(va.x - hx));
            hx = __uint_as_float(rna(va.y)); ah[1] = hx; al[1] = __uint_as_float(rna(va.y - hx));
            hx = __uint_as_float(rna(va.z)); ah[2] = hx; al[2] = __uint_as_float(rna(va.z - hx));
            hx = __uint_as_float(rna(va.w)); ah[3] = hx; al[3] = __uint_as_float(rna(va.w - hx));
            float4 vb = *(const float4*)(w + (size_t)r * 128 + kc * 32 + f4 * 4);
            float* bh = Bh + r * 36 + f4 * 4;
            float* bl = Bl + r * 36 + f4 * 4;
            hx = __uint_as_float(rna(vb.x)); bh[0] = hx; bl[0] = __uint_as_float(rna(vb.x - hx));
            hx = __uint_as_float(rna(vb.y)); bh[1] = hx; bl[1] = __uint_as_float(rna(vb.y - hx));
            hx = __uint_as_float(rna(vb.z)); bh[2] = hx; bl[2] = __uint_as_float(rna(vb.z - hx));
            hx = __uint_as_float(rna(vb.w)); bh[3] = hx; bl[3] = __uint_as_float(rna(vb.w - hx));
        }
        __syncthreads();

        #pragma unroll
        for (int ks = 0; ks < 4; ks++) {
            int ar = wm * 32 + (lane >> 2), ac = ks * 8 + (lane & 3);
            unsigned ahf[2][4], alf[2][4];
            #pragma unroll
            for (int mi = 0; mi < 2; mi++) {
                int base = (ar + mi * 16) * 36 + ac;
                ahf[mi][0] = f2u(Ah[base]);         ahf[mi][1] = f2u(Ah[base + 8 * 36]);
                ahf[mi][2] = f2u(Ah[base + 4]);     ahf[mi][3] = f2u(Ah[base + 8 * 36 + 4]);
                alf[mi][0] = f2u(Al[base]);         alf[mi][1] = f2u(Al[base + 8 * 36]);
                alf[mi][2] = f2u(Al[base + 4]);     alf[mi][3] = f2u(Al[base + 8 * 36 + 4]);
            }
            int bn = wn * 32 + (lane >> 2), bk = ks * 8 + (lane & 3);
            unsigned bhf[4][2], blf[4][2];
            #pragma unroll
            for (int nj = 0; nj < 4; nj++) {
                int bb = (bn + nj * 8) * 36 + bk;
                bhf[nj][0] = f2u(Bh[bb]); bhf[nj][1] = f2u(Bh[bb + 4]);
                blf[nj][0] = f2u(Bl[bb]); blf[nj][1] = f2u(Bl[bb + 4]);
            }
            #pragma unroll
            for (int mi = 0; mi < 2; mi++)
                #pragma unroll
                for (int nj = 0; nj < 4; nj++) {
                    mma8(d[mi][nj], ahf[mi], bhf[nj]);
                    mma8(d[mi][nj], ahf[mi], blf[nj]);
                    mma8(d[mi][nj], alf[mi], bhf[nj]);
                }
        }
        __syncthreads();
    }

    #pragma unroll
    for (int mi = 0; mi < 2; mi++) {
        int ml = wm * 32 + mi * 16 + (lane >> 2);
        #pragma unroll
        for (int nj = 0; nj < 4; nj++) {
            int col = wn * 32 + nj * 8 + (lane & 3) * 2;
            float2 bv = *(const float2*)(bias + col);
            float2 o0, o1;
            o0.x = d[mi][nj][0] + bv.x; o0.y = d[mi][nj][1] + bv.y;
            o1.x = d[mi][nj][2] + bv.x; o1.y = d[mi][nj][3] + bv.y;
            *(float2*)(out + rowdst[ml] + col) = o0;
            *(float2*)(out + rowdst[ml + 8] + col) = o1;
        }
    }
}

// ---------------------------------------------------------------------------
extern "C" void kernel_launch(void* const* d_in, const int* in_sizes, int n_in,
                              void* d_out, int out_size)
{
    const float* x   = (const float*)d_in[0];
    const float* qw  = (const float*)d_in[1];
    const float* qb  = (const float*)d_in[2];
    const float* pw  = (const float*)d_in[3];
    const float* pb  = (const float*)d_in[4];
    const float* rpb = (const float*)d_in[5];
    float* out = (float*)d_out;

    const int smemG = 4 * 4608 * 4 + 128 * 4;                       // 74,240 B
    const int smemA = (14112 + 15680 + 2304 + 25344 + 64) * 4 + 400; // 230,416 B

    cudaFuncSetAttribute(qkv_kernel,  cudaFuncAttributeMaxDynamicSharedMemorySize, smemG);
    cudaFuncSetAttribute(attn_kernel, cudaFuncAttributeMaxDynamicSharedMemorySize, smemA);
    cudaFuncSetAttribute(proj_kernel, cudaFuncAttributeMaxDynamicSharedMemorySize, smemG);

    qkv_kernel<<<dim3(784, 3), 512, smemG>>>(x, qw, qb);
    attn_kernel<<<1024, 512, smemA>>>(rpb);
    proj_kernel<<<784, 512, smemG>>>(pw, pb, out);
}